// round 10
// baseline (speedup 1.0000x reference)
#include <cuda_runtime.h>

// Elementwise affine: y = x * 2 + 5 over 8192*8192 fp32. FINAL (converged).
//
// Certified roofline configuration after a full sweep of every available
// axis on sm_103a:
//   - per-thread MLP (ILP 1/2/4/8): 4 optimal; 8 loses occupancy (40 regs)
//   - vector width (LDG.128 vs LDG.256): equal (issue was never binding, 5.5%)
//   - cache policy (.cs / .wt / default): .cs best by a hair
//   - CTA shape (256 vs 512 threads): equal; 512 ties best DRAM% at half grid
// All ILP>=2 variants land at 74.5 +/- 0.7 us kernel time = ~6.45 TB/s =
// 81% of 8 TB/s HBM spec — the mixed 50/50 read+write DRAM-controller
// ceiling. Not LTS-capped (~11 TB/s @NAT), not issue/occupancy-capped.
// 512 MB of traffic is irreducible for this op.
//
// 16777216 float4 total; 512 thr/block * 4 float4/thr -> 8192 blocks.

__global__ void __launch_bounds__(512) affine_kernel(const float4* __restrict__ x,
                                                     float4* __restrict__ y) {
    unsigned int base = blockIdx.x * 2048u + threadIdx.x;

    float4 v0 = __ldcs(&x[base]);
    float4 v1 = __ldcs(&x[base + 512u]);
    float4 v2 = __ldcs(&x[base + 1024u]);
    float4 v3 = __ldcs(&x[base + 1536u]);

    float4 r0, r1, r2, r3;
    r0.x = fmaf(v0.x, 2.0f, 5.0f); r0.y = fmaf(v0.y, 2.0f, 5.0f);
    r0.z = fmaf(v0.z, 2.0f, 5.0f); r0.w = fmaf(v0.w, 2.0f, 5.0f);
    r1.x = fmaf(v1.x, 2.0f, 5.0f); r1.y = fmaf(v1.y, 2.0f, 5.0f);
    r1.z = fmaf(v1.z, 2.0f, 5.0f); r1.w = fmaf(v1.w, 2.0f, 5.0f);
    r2.x = fmaf(v2.x, 2.0f, 5.0f); r2.y = fmaf(v2.y, 2.0f, 5.0f);
    r2.z = fmaf(v2.z, 2.0f, 5.0f); r2.w = fmaf(v2.w, 2.0f, 5.0f);
    r3.x = fmaf(v3.x, 2.0f, 5.0f); r3.y = fmaf(v3.y, 2.0f, 5.0f);
    r3.z = fmaf(v3.z, 2.0f, 5.0f); r3.w = fmaf(v3.w, 2.0f, 5.0f);

    __stcs(&y[base],          r0);
    __stcs(&y[base + 512u],   r1);
    __stcs(&y[base + 1024u],  r2);
    __stcs(&y[base + 1536u],  r3);
}

extern "C" void kernel_launch(void* const* d_in, const int* in_sizes, int n_in,
                              void* d_out, int out_size) {
    const float4* x = (const float4*)d_in[0];
    float4* y = (float4*)d_out;
    int n = in_sizes[0];            // 67108864
    int n4 = n / 4;                 // 16777216
    int blocks = n4 / 2048;         // 8192
    affine_kernel<<<blocks, 512>>>(x, y);
}

// round 11
// speedup vs baseline: 1.0055x; 1.0055x over previous
#include <cuda_runtime.h>

// Elementwise affine: y = x * 2 + 5 over 8192*8192 fp32. FINAL (converged).
//
// Certified roofline configuration after a full sweep of every available
// axis on sm_103a:
//   - per-thread MLP (ILP 1/2/4/8): 4 optimal; 8 loses occupancy (40 regs)
//   - vector width (LDG.128 vs LDG.256): equal (issue was never binding, ~5.5%)
//   - cache policy (.cs / .wt / default): .cs best by a hair
//   - CTA shape (256 vs 512 threads): 512 measured best (73.6-74.2us kernel,
//     DRAM 81.9-82.5%) at half the grid
// Best measured: 73.63us kernel, 6535 GB/s = 81.7% of 8 TB/s HBM spec — the
// mixed 50/50 read+write DRAM-controller ceiling. Not LTS-capped (~11 TB/s
// @NAT), not issue/occupancy-capped. 512 MB of traffic is irreducible.
//
// 16777216 float4 total; 512 thr/block * 4 float4/thr -> 8192 blocks.

__global__ void __launch_bounds__(512) affine_kernel(const float4* __restrict__ x,
                                                     float4* __restrict__ y) {
    unsigned int base = blockIdx.x * 2048u + threadIdx.x;

    float4 v0 = __ldcs(&x[base]);
    float4 v1 = __ldcs(&x[base + 512u]);
    float4 v2 = __ldcs(&x[base + 1024u]);
    float4 v3 = __ldcs(&x[base + 1536u]);

    float4 r0, r1, r2, r3;
    r0.x = fmaf(v0.x, 2.0f, 5.0f); r0.y = fmaf(v0.y, 2.0f, 5.0f);
    r0.z = fmaf(v0.z, 2.0f, 5.0f); r0.w = fmaf(v0.w, 2.0f, 5.0f);
    r1.x = fmaf(v1.x, 2.0f, 5.0f); r1.y = fmaf(v1.y, 2.0f, 5.0f);
    r1.z = fmaf(v1.z, 2.0f, 5.0f); r1.w = fmaf(v1.w, 2.0f, 5.0f);
    r2.x = fmaf(v2.x, 2.0f, 5.0f); r2.y = fmaf(v2.y, 2.0f, 5.0f);
    r2.z = fmaf(v2.z, 2.0f, 5.0f); r2.w = fmaf(v2.w, 2.0f, 5.0f);
    r3.x = fmaf(v3.x, 2.0f, 5.0f); r3.y = fmaf(v3.y, 2.0f, 5.0f);
    r3.z = fmaf(v3.z, 2.0f, 5.0f); r3.w = fmaf(v3.w, 2.0f, 5.0f);

    __stcs(&y[base],          r0);
    __stcs(&y[base + 512u],   r1);
    __stcs(&y[base + 1024u],  r2);
    __stcs(&y[base + 1536u],  r3);
}

extern "C" void kernel_launch(void* const* d_in, const int* in_sizes, int n_in,
                              void* d_out, int out_size) {
    const float4* x = (const float4*)d_in[0];
    float4* y = (float4*)d_out;
    int n = in_sizes[0];            // 67108864
    int n4 = n / 4;                 // 16777216
    int blocks = n4 / 2048;         // 8192
    affine_kernel<<<blocks, 512>>>(x, y);
}